// round 15
// baseline (speedup 1.0000x reference)
#include <cuda_runtime.h>
#include <cuda_fp16.h>
#include <math.h>
#include <stdint.h>
#include <mma.h>

using namespace nvcuda;

#define Bb   4
#define Dm   768
#define Tt   14
#define Np   196
#define NH   12
#define HD   64
#define FFD  3072
#define BN   (Bb*Np)       // 784
#define HW   224
#define CHW  (HW*HW)       // 50176
#define MP   896           // padded M for 128-tiles

#define TLDH 776           // padded fp16 tile stride (conflict-free, 16B-aligned)
#define DLD  20
#define ELDH 24

// ---------------- scratch ----------------
__device__ __half g_xh [(size_t)Bb*Dm*CHW];
__device__ __half g_qh [BN*Dm];
__device__ __half g_qph[BN*Dm];
__device__ __half g_qkwh[BN*NH*Dm];
__device__ __half g_avnh[BN*NH*Dm];
__device__ __half g_ctxh[BN*Dm];
__device__ __half g_o1h[BN*Dm];
__device__ __half g_h1h[BN*FFD];
__device__ float  g_part[(size_t)4*MP*Dm];      // split-K partials (fc2 only)
#define W_IN_OFF   0
#define W_OUT_OFF  (3*Dm*Dm)
#define W_FC1_OFF  (W_OUT_OFF + Dm*Dm)
#define W_FC2_OFF  (W_FC1_OFF + FFD*Dm)
#define W_TOTAL    (W_FC2_OFF + Dm*FFD)
__device__ __half g_wh[W_TOTAL];

#define MEAN_BLOCKS (Bb*Dm*Tt)                   // 43008
#define F2H_CHUNKS  (W_TOTAL/4)
#define F2H_BLOCKS  ((F2H_CHUNKS + 223)/224)

__device__ __forceinline__ void cp_async16(uint32_t dst, const void* src) {
    asm volatile("cp.async.cg.shared.global [%0], [%1], 16;" :: "r"(dst), "l"(src));
}

// ---------------- fused prep: token means + x->fp16 + weight conversion ----------------
__global__ void prep_kernel(const float* __restrict__ x,
                            const float* __restrict__ s0, const float* __restrict__ s1,
                            const float* __restrict__ s2, const float* __restrict__ s3,
                            __half* __restrict__ wd) {
    int bid = blockIdx.x;
    if (bid >= MEAN_BLOCKS) {
        int chunk = (bid - MEAN_BLOCKS)*224 + threadIdx.x;
        int i = chunk*4;
        if (i >= W_TOTAL) return;
        const float* s; int off;
        if      (i < W_OUT_OFF) { s = s0; off = 0; }
        else if (i < W_FC1_OFF) { s = s1; off = W_OUT_OFF; }
        else if (i < W_FC2_OFF) { s = s2; off = W_FC1_OFF; }
        else                    { s = s3; off = W_FC2_OFF; }
        float4 v = *(const float4*)(s + (i - off));
        ((__half2*)(wd + i))[0] = __floats2half2_rn(v.x, v.y);
        ((__half2*)(wd + i))[1] = __floats2half2_rn(v.z, v.w);
        return;
    }
    int t1 = bid % Tt;
    int dd = (bid / Tt) % Dm;
    int b  = bid / (Tt * Dm);
    size_t base = ((size_t)b*Dm + dd)*CHW + (size_t)t1*16*HW;
    const float4* xp = (const float4*)(x + base);
    __half* xo = g_xh + base;

    int t  = threadIdx.x;
    int qi = t % 56;
    int rg = t / 56;

    float4 acc = make_float4(0.f, 0.f, 0.f, 0.f);
    #pragma unroll
    for (int k = 0; k < 4; k++) {
        int r = rg*4 + k;
        float4 v = xp[r*56 + qi];
        acc.x += v.x; acc.y += v.y; acc.z += v.z; acc.w += v.w;
        __half2 h0 = __floats2half2_rn(v.x, v.y);
        __half2 h1 = __floats2half2_rn(v.z, v.w);
        uint2 u;
        u.x = *(uint32_t*)&h0;
        u.y = *(uint32_t*)&h1;
        *(uint2*)(xo + (size_t)r*HW + qi*4) = u;
    }

    __shared__ float4 ps[224];
    __shared__ float qsum[56];
    ps[t] = acc;
    __syncthreads();
    if (t < 56) {
        float s = 0.f;
        #pragma unroll
        for (int r2 = 0; r2 < 4; r2++) {
            float4 v = ps[r2*56 + t];
            s += v.x + v.y + v.z + v.w;
        }
        qsum[t] = s;
    }
    __syncthreads();
    if (t < Tt) {
        float s = qsum[4*t] + qsum[4*t+1] + qsum[4*t+2] + qsum[4*t+3];
        g_qh[((size_t)b*Np + t1*Tt + t)*Dm + dd] = __float2half(s * (1.0f/256.0f));
    }
}

// ---------------- 128x128 fp16 GEMM (TRANSB) ----------------
__global__ __launch_bounds__(256) void gemm128(
    const __half* __restrict__ A, const __half* __restrict__ Bm,
    float* __restrict__ P, int M, int N, int K, int lda, int ldb, int KS,
    const float* __restrict__ bias, __half* __restrict__ out16, int silu)
{
    extern __shared__ __half dbuf[];
    uint32_t sb = (uint32_t)__cvta_generic_to_shared(dbuf);

    int m0 = blockIdx.y * 128, n0 = blockIdx.x * 128;
    int z = blockIdx.z;
    int Ksub = K / KS;
    int kbase = z * Ksub;
    int tid = threadIdx.x;
    int warpId = tid >> 5;
    int wm = warpId >> 2;
    int wn = warpId & 3;

    wmma::fragment<wmma::accumulator, 16, 16, 16, float> acc[4][2];
    #pragma unroll
    for (int i = 0; i < 4; i++)
        #pragma unroll
        for (int j = 0; j < 2; j++) wmma::fill_fragment(acc[i][j], 0.f);

    const int nk = Ksub >> 6;

    auto issue = [&](int it, int s) {
        int k0 = kbase + it*64;
        uint32_t abase = sb + (uint32_t)(s * 18432 * 2);
        uint32_t bbase = abase + 9216*2;
        #pragma unroll
        for (int i = 0; i < 4; i++) {
            int idx = tid + 256*i;
            int row = idx >> 3, seg = idx & 7;
            int m = m0 + row; if (m >= M) m = M - 1;
            cp_async16(abase + (uint32_t)((row*72 + seg*8)*2),
                       A + (size_t)m*lda + k0 + seg*8);
        }
        #pragma unroll
        for (int i = 0; i < 4; i++) {
            int idx = tid + 256*i;
            int nn = idx >> 3, seg = idx & 7;
            int ng = n0 + nn; if (ng >= N) ng = N - 1;
            cp_async16(bbase + (uint32_t)((nn*72 + seg*8)*2),
                       Bm + (size_t)ng*ldb + k0 + seg*8);
        }
        asm volatile("cp.async.commit_group;");
    };

    issue(0, 0);

    for (int it = 0; it < nk; it++) {
        int s = it & 1;
        if (it + 1 < nk) {
            issue(it+1, s^1);
            asm volatile("cp.async.wait_group 1;");
        } else {
            asm volatile("cp.async.wait_group 0;");
        }
        __syncthreads();

        const __half* As = dbuf + s*18432;
        const __half* Bs = As + 9216;

        #pragma unroll
        for (int ks = 0; ks < 4; ks++) {
            wmma::fragment<wmma::matrix_b, 16, 16, 16, __half, wmma::col_major> bf[2];
            #pragma unroll
            for (int j = 0; j < 2; j++)
                wmma::load_matrix_sync(bf[j], Bs + (wn*32 + j*16)*72 + ks*16, 72);
            #pragma unroll
            for (int i = 0; i < 4; i++) {
                wmma::fragment<wmma::matrix_a, 16, 16, 16, __half, wmma::row_major> af;
                wmma::load_matrix_sync(af, As + (wm*64 + i*16)*72 + ks*16, 72);
                #pragma unroll
                for (int j = 0; j < 2; j++)
                    wmma::mma_sync(acc[i][j], af, bf[j], acc[i][j]);
            }
        }
        __syncthreads();
    }

    if (!bias) {
        float* base = P + (size_t)z*MP*N;
        #pragma unroll
        for (int i = 0; i < 4; i++)
            #pragma unroll
            for (int j = 0; j < 2; j++)
                wmma::store_matrix_sync(base + (size_t)(m0 + wm*64 + i*16)*N + n0 + wn*32 + j*16,
                                        acc[i][j], N, wmma::mem_row_major);
    } else {
        float* Cs = (float*)dbuf;
        #pragma unroll
        for (int i = 0; i < 4; i++)
            #pragma unroll
            for (int j = 0; j < 2; j++)
                wmma::store_matrix_sync(Cs + (wm*64 + i*16)*132 + wn*32 + j*16,
                                        acc[i][j], 132, wmma::mem_row_major);
        __syncthreads();
        #pragma unroll
        for (int i = 0; i < 16; i++) {
            int e = tid + 256*i;
            int row = e >> 5, seg = e & 31;
            int m = m0 + row, nb = n0 + seg*4;
            if (m >= M || nb >= N) continue;
            float4 v = *(const float4*)(Cs + row*132 + seg*4);
            float4 bv = *(const float4*)(bias + nb);
            v.x += bv.x; v.y += bv.y; v.z += bv.z; v.w += bv.w;
            if (silu) {
                v.x = v.x/(1.f+__expf(-v.x)); v.y = v.y/(1.f+__expf(-v.y));
                v.z = v.z/(1.f+__expf(-v.z)); v.w = v.w/(1.f+__expf(-v.w));
            }
            __half2* dst = (__half2*)(out16 + (size_t)m*N + nb);
            dst[0] = __floats2half2_rn(v.x, v.y);
            dst[1] = __floats2half2_rn(v.z, v.w);
        }
    }
}

// ---------------- split-K epilogue (fc2 only) ----------------
__global__ void epi_kernel(const float* __restrict__ P, const float* __restrict__ bias,
                           float* __restrict__ out32, __half* __restrict__ out16,
                           int MN, int N, int KS, float gamma, int silu)
{
    int i = (blockIdx.x*256 + threadIdx.x)*4;
    if (i >= MN) return;
    int c = i % N;
    float4 s = *(const float4*)(P + i);
    for (int ks = 1; ks < KS; ks++) {
        float4 p = *(const float4*)(P + (size_t)ks*MP*N + i);
        s.x += p.x; s.y += p.y; s.z += p.z; s.w += p.w;
    }
    float4 bv = *(const float4*)(bias + c);
    s.x = (s.x + bv.x)*gamma; s.y = (s.y + bv.y)*gamma;
    s.z = (s.z + bv.z)*gamma; s.w = (s.w + bv.w)*gamma;
    if (silu) {
        s.x = s.x/(1.f+__expf(-s.x)); s.y = s.y/(1.f+__expf(-s.y));
        s.z = s.z/(1.f+__expf(-s.z)); s.w = s.w/(1.f+__expf(-s.w));
    }
    if (out32) *(float4*)(out32 + i) = s;
    if (out16) {
        ((__half2*)(out16 + i))[0] = __floats2half2_rn(s.x, s.y);
        ((__half2*)(out16 + i))[1] = __floats2half2_rn(s.z, s.w);
    }
}

// ---------------- 64x64 fp16 GEMM (qp / qkw / ctx / o1; fused epilogue) ----------------
template<bool TRANSB>
__global__ __launch_bounds__(256) void gemm_hc(
    const __half* __restrict__ A, const __half* __restrict__ Bm,
    const float* __restrict__ bias, float* __restrict__ C32, __half* __restrict__ C16,
    int M, int N, int K, int lda, int ldb, int ldc,
    int sAh, int sBh, int sCh, int sBiasH,
    float gamma, int silu)
{
    int h = blockIdx.z;
    A  += (size_t)h * sAh;
    Bm += (size_t)h * sBh;
    const float* biasp = bias ? bias + (size_t)h * sBiasH : nullptr;

    __shared__ __half hbuf[2*2*64*72];
    uint32_t sb = (uint32_t)__cvta_generic_to_shared(hbuf);

    int m0 = blockIdx.y * 64, n0 = blockIdx.x * 64;
    int tid = threadIdx.x;
    int warpId = tid >> 5;
    int wm = warpId >> 1;
    int wn = warpId & 1;

    wmma::fragment<wmma::accumulator, 16, 16, 16, float> cf[2];
    wmma::fill_fragment(cf[0], 0.f);
    wmma::fill_fragment(cf[1], 0.f);

    const int nk = K >> 6;

    auto issue = [&](int it, int s) {
        int k0 = it * 64;
        uint32_t abase = sb + (uint32_t)(s * 9216 * 2);
        uint32_t bbase = abase + 4608*2;
        #pragma unroll
        for (int i = 0; i < 2; i++) {
            int idx = tid + 256*i;
            int row = idx >> 3, seg = idx & 7;
            int m = m0 + row; if (m >= M) m = M - 1;
            cp_async16(abase + (uint32_t)((row*72 + seg*8)*2),
                       A + (size_t)m*lda + k0 + seg*8);
        }
        if (TRANSB) {
            #pragma unroll
            for (int i = 0; i < 2; i++) {
                int idx = tid + 256*i;
                int nn = idx >> 3, seg = idx & 7;
                int ng = n0 + nn; if (ng >= N) ng = N - 1;
                cp_async16(bbase + (uint32_t)((nn*72 + seg*8)*2),
                           Bm + (size_t)ng*ldb + k0 + seg*8);
            }
        } else {
            #pragma unroll
            for (int i = 0; i < 2; i++) {
                int idx = tid + 256*i;
                int kk = idx >> 3, seg = idx & 7;
                int nb = n0 + seg*8; if (nb >= N) nb = 0;
                cp_async16(bbase + (uint32_t)((kk*72 + seg*8)*2),
                           Bm + (size_t)(k0+kk)*ldb + nb);
            }
        }
        asm volatile("cp.async.commit_group;");
    };

    issue(0, 0);

    for (int it = 0; it < nk; it++) {
        int s = it & 1;
        if (it + 1 < nk) {
            issue(it+1, s^1);
            asm volatile("cp.async.wait_group 1;");
        } else {
            asm volatile("cp.async.wait_group 0;");
        }
        __syncthreads();

        const __half* As = hbuf + s*9216;
        const __half* Bs = As + 4608;

        #pragma unroll
        for (int ks = 0; ks < 4; ks++) {
            wmma::fragment<wmma::matrix_a, 16, 16, 16, __half, wmma::row_major> af;
            wmma::load_matrix_sync(af, As + (wm*16)*72 + ks*16, 72);
            #pragma unroll
            for (int j = 0; j < 2; j++) {
                if (TRANSB) {
                    wmma::fragment<wmma::matrix_b, 16, 16, 16, __half, wmma::col_major> bf;
                    wmma::load_matrix_sync(bf, Bs + (wn*32 + j*16)*72 + ks*16, 72);
                    wmma::mma_sync(cf[j], af, bf, cf[j]);
                } else {
                    wmma::fragment<wmma::matrix_b, 16, 16, 16, __half, wmma::row_major> bf;
                    wmma::load_matrix_sync(bf, Bs + (ks*16)*72 + wn*32 + j*16, 72);
                    wmma::mma_sync(cf[j], af, bf, cf[j]);
                }
            }
        }
        __syncthreads();
    }

    float (*Cs)[68] = (float(*)[68])hbuf;
    wmma::store_matrix_sync(&Cs[wm*16][wn*32],      cf[0], 68, wmma::mem_row_major);
    wmma::store_matrix_sync(&Cs[wm*16][wn*32 + 16], cf[1], 68, wmma::mem_row_major);
    __syncthreads();

    #pragma unroll
    for (int i = 0; i < 4; i++) {
        int e = tid + 256*i;
        int row = e >> 4, seg = e & 15;
        int m = m0 + row, nbase = n0 + seg*4;
        if (m >= M || nbase >= N) continue;
        float4 v = *(const float4*)&Cs[row][seg*4];
        if (biasp) {
            float4 bv = *(const float4*)(biasp + nbase);
            v.x += bv.x; v.y += bv.y; v.z += bv.z; v.w += bv.w;
        }
        v.x *= gamma; v.y *= gamma; v.z *= gamma; v.w *= gamma;
        if (silu) {
            v.x = v.x/(1.f+__expf(-v.x)); v.y = v.y/(1.f+__expf(-v.y));
            v.z = v.z/(1.f+__expf(-v.z)); v.w = v.w/(1.f+__expf(-v.w));
        }
        if (C32) *(float4*)(C32 + (size_t)m*ldc + nbase + (size_t)h*sCh) = v;
        if (C16) {
            __half2* dst = (__half2*)(C16 + (size_t)m*ldc + nbase + (size_t)h*sCh);
            dst[0] = __floats2half2_rn(v.x, v.y);
            dst[1] = __floats2half2_rn(v.z, v.w);
        }
    }
}

// ---------------- fused attention v7d: 2-barrier pipeline, AV lags scores by one chunk ----------------
// smem: qkw 18624 | tiles 3x24832 | Dpart 15360 | e_s 768 | e_hr 2x768 | denom 64 = 110848 B
__global__ __launch_bounds__(384, 2) void attn7() {
    extern __shared__ __half smh[];
    __half* qkw_s = smh;                          // [12][TLDH]
    __half* tiles = smh + 12*TLDH;                // 3 x [16][TLDH]
    float*  Dpart = (float*)(smh + 60*TLDH);      // [12][16][DLD]
    float*  e_s   = Dpart + 12*16*DLD;            // [192] final denom reduce
    __half* e_hr  = (__half*)(e_s + 192);         // 2 x [16][ELDH]
    float*  denom = (float*)(e_hr + 2*16*ELDH);   // 16

    int bn = blockIdx.x;
    int b = bn / Np, n = bn % Np;
    int t1 = n / Tt, t2 = n % Tt;
    const __half* xph = g_xh + (size_t)b*Dm*CHW + (size_t)(t1*16)*HW + t2*16;

    int tid = threadIdx.x, w = tid >> 5;

    auto issue_chunk = [&](int lc) {
        uint32_t stp = (uint32_t)__cvta_generic_to_shared(tiles + (lc % 3)*16*TLDH);
        #pragma unroll
        for (int j = 0; j < 4; j++) {
            int ch = tid + 384*j;
            int idx8 = ch*8;
            int r = idx8 / 768, cc = idx8 - r*768;
            int flat = lc*12288 + idx8;
            int dd = flat >> 8, g1 = (flat >> 4) & 15, g2 = flat & 15;
            cp_async16(stp + (uint32_t)((r*TLDH + cc)*2), xph + (size_t)dd*CHW + g1*HW + g2);
        }
        asm volatile("cp.async.commit_group;");
    };

    issue_chunk(0);
    issue_chunk(1);

    {
        const __half* src = g_qkwh + (size_t)bn*(NH*Dm);
        #pragma unroll
        for (int i = 0; i < 3; i++) {
            int idx = tid + 384*i;
            int hh = idx / 96, rem = idx - hh*96;
            *(float4*)(qkw_s + hh*TLDH + rem*8) = *(const float4*)(src + idx*8);
        }
    }
    // zero both e_hr buffers (pad heads 12..15 stay zero forever)
    e_hr[tid] = __float2half(0.f);
    e_hr[tid + 384] = __float2half(0.f);

    float myden = 0.f;
    int my_r = tid / 12, my_h = tid - my_r*12;

    wmma::fragment<wmma::accumulator, 16, 16, 16, float> av[4];
    #pragma unroll
    for (int ct = 0; ct < 4; ct++) wmma::fill_fragment(av[ct], 0.f);

    for (int i = 0; i <= 16; i++) {
        if (i < 16) {
            if (i < 15) asm volatile("cp.async.wait_group 1;");
            else        asm volatile("cp.async.wait_group 0;");
        }
        __syncthreads();   // sync A: tile(i) visible; e_hr[(i-1)&1] from last iter visible

        // AV for chunk i-1 (tile (i-1)%3 still live; overwritten only after sync B)
        if (i >= 1) {
            const __half* prev = tiles + ((i-1) % 3)*16*TLDH;
            wmma::fragment<wmma::matrix_a, 16, 16, 16, __half, wmma::row_major> ef;
            wmma::load_matrix_sync(ef, e_hr + ((i-1)&1)*16*ELDH, ELDH);
            #pragma unroll
            for (int ct = 0; ct < 4; ct++) {
                wmma::fragment<wmma::matrix_b, 16, 16, 16, __half, wmma::row_major> vb;
                wmma::load_matrix_sync(vb, prev + w*64 + ct*16, TLDH);
                wmma::mma_sync(av[ct], ef, vb, av[ct]);
            }
        }
        // scores for chunk i
        if (i < 16) {
            const __half* cur = tiles + (i % 3)*16*TLDH;
            wmma::fragment<wmma::accumulator, 16, 16, 16, float> d;
            wmma::fill_fragment(d, 0.f);
            #pragma unroll
            for (int ks = 0; ks < 4; ks++) {
                int k = w*64 + ks*16;
                wmma::fragment<wmma::matrix_a, 16, 16, 16, __half, wmma::row_major> af;
                wmma::load_matrix_sync(af, cur + k, TLDH);
                wmma::fragment<wmma::matrix_b, 16, 16, 16, __half, wmma::col_major> bf;
                wmma::load_matrix_sync(bf, qkw_s + k, TLDH);
                wmma::mma_sync(d, af, bf, d);
            }
            wmma::store_matrix_sync(Dpart + w*16*DLD, d, DLD, wmma::mem_row_major);
        }
        __syncthreads();   // sync B: Dpart ready; AV(i-1) done -> buffer (i-1)%3 free

        if (i + 2 <= 15) issue_chunk(i + 2);   // fills (i+2)%3 == (i-1)%3, now free

        if (i < 16 && tid < 192) {
            float s = 0.f;
            #pragma unroll
            for (int w2 = 0; w2 < 12; w2++) s += Dpart[w2*16*DLD + my_r*DLD + my_h];
            float e = __expf(s);
            myden += e;
            e_hr[(i&1)*16*ELDH + my_h*ELDH + my_r] = __float2half(e);
        }
    }

    // finalize denominators
    if (tid < 192) e_s[tid] = myden;
    __syncthreads();
    if (tid < NH) {
        float d = 0.f;
        #pragma unroll
        for (int r = 0; r < 16; r++) d += e_s[r*12 + tid];
        denom[tid] = d;
    }

    // stage AV accumulators, normalize, write fp16
    float* stage = (float*)smh;                // [16][772]
    #pragma unroll
    for (int ct = 0; ct < 4; ct++)
        wmma::store_matrix_sync(stage + w*64 + ct*16, av[ct], 772, wmma::mem_row_major);
    __syncthreads();

    float4 d0 = *(const float4*)(denom);
    float4 d1 = *(const float4*)(denom + 4);
    float4 d2 = *(const float4*)(denom + 8);
    float inv[NH] = {1.f/d0.x, 1.f/d0.y, 1.f/d0.z, 1.f/d0.w,
                     1.f/d1.x, 1.f/d1.y, 1.f/d1.z, 1.f/d1.w,
                     1.f/d2.x, 1.f/d2.y, 1.f/d2.z, 1.f/d2.w};
    #pragma unroll
    for (int hh = 0; hh < NH; hh++) {
        float a = stage[hh*772 + tid*2]     * inv[hh];
        float c = stage[hh*772 + tid*2 + 1] * inv[hh];
        *(__half2*)(g_avnh + (size_t)bn*(NH*Dm) + hh*768 + tid*2) = __floats2half2_rn(a, c);
    }
}

// ---------------- host ----------------
extern "C" void kernel_launch(void* const* d_in, const int* in_sizes, int n_in,
                              void* d_out, int out_size)
{
    const float* x     = (const float*)d_in[0];
    const float* w_in  = (const float*)d_in[1];
    const float* b_in  = (const float*)d_in[2];
    const float* w_out = (const float*)d_in[3];
    const float* b_out = (const float*)d_in[4];
    const float* w_fc1 = (const float*)d_in[5];
    const float* b_fc1 = (const float*)d_in[6];
    const float* w_fc2 = (const float*)d_in[7];
    const float* b_fc2 = (const float*)d_in[8];
    float* y = (float*)d_out;

    __half *qh, *qph, *qkwh, *avnh, *ctxh, *o1h, *h1h, *wh;
    float *part;
    cudaGetSymbolAddress((void**)&qh,   g_qh);
    cudaGetSymbolAddress((void**)&qph,  g_qph);
    cudaGetSymbolAddress((void**)&qkwh, g_qkwh);
    cudaGetSymbolAddress((void**)&avnh, g_avnh);
    cudaGetSymbolAddress((void**)&ctxh, g_ctxh);
    cudaGetSymbolAddress((void**)&o1h,  g_o1h);
    cudaGetSymbolAddress((void**)&h1h,  g_h1h);
    cudaGetSymbolAddress((void**)&wh,   g_wh);
    cudaGetSymbolAddress((void**)&part, g_part);

    const int GSMEM = 2*18432*2;
    cudaFuncSetAttribute(gemm128, cudaFuncAttributeMaxDynamicSharedMemorySize, GSMEM);

    // 0+1. fused weight conversion + token means + x->fp16
    prep_kernel<<<MEAN_BLOCKS + F2H_BLOCKS, 224>>>(x, w_in, w_out, w_fc1, w_fc2, wh);

    // 2. qp = (q @ wq^T + bq)*0.125
    gemm_hc<true><<<dim3(12,13,1), 256>>>(qh, wh + W_IN_OFF, b_in, nullptr, qph,
        BN, Dm, Dm, Dm, Dm, Dm, 0,0,0,0, 0.125f, 0);

    // 3. qkw  (batched heads, K=64)
    gemm_hc<false><<<dim3(12,13,NH), 256>>>(qph, wh + W_IN_OFF + Dm*Dm, nullptr, nullptr, qkwh,
        BN, Dm, HD, Dm, Dm, NH*Dm, HD, HD*Dm, Dm, 0, 1.f, 0);

    // 4. fused attention (2-barrier pipeline)
    {
        static const size_t smem = 110848;
        cudaFuncSetAttribute(attn7, cudaFuncAttributeMaxDynamicSharedMemorySize, (int)smem);
        attn7<<<BN, 384, smem>>>();
    }

    // 5. ctx  (batched heads)
    gemm_hc<true><<<dim3(1,13,NH), 256>>>(avnh, wh + W_IN_OFF + 2*Dm*Dm, b_in + 2*Dm, nullptr, ctxh,
        BN, HD, Dm, NH*Dm, Dm, Dm, Dm, HD*Dm, HD, HD, 1.f, 0);

    // 6. o1 = ctx @ w_out^T + b_out
    gemm_hc<true><<<dim3(12,13,1), 256>>>(ctxh, wh + W_OUT_OFF, b_out, nullptr, o1h,
        BN, Dm, Dm, Dm, Dm, Dm, 0,0,0,0, 1.f, 0);

    // 7. h1 = silu(o1 @ w_fc1^T + b_fc1)
    gemm128<<<dim3(24,7,1), 256, GSMEM>>>(o1h, wh + W_FC1_OFF, part, BN, FFD, Dm, Dm, Dm, 1,
                                          b_fc1, h1h, 1);

    // 8. y = h1 @ w_fc2^T + b_fc2  (split-K 4)
    gemm128<<<dim3(6,7,4), 256, GSMEM>>>(h1h, wh + W_FC2_OFF, part, BN, Dm, FFD, FFD, FFD, 4,
                                         nullptr, nullptr, 0);
    epi_kernel<<<(BN*Dm/4 + 255)/256, 256>>>(part, b_fc2, y, nullptr, BN*Dm, Dm, 4, 1.f, 0);
}

// round 16
// speedup vs baseline: 1.0041x; 1.0041x over previous
#include <cuda_runtime.h>
#include <cuda_fp16.h>
#include <math.h>
#include <stdint.h>
#include <mma.h>

using namespace nvcuda;

#define Bb   4
#define Dm   768
#define Tt   14
#define Np   196
#define NH   12
#define HD   64
#define FFD  3072
#define BN   (Bb*Np)       // 784
#define HW   224
#define CHW  (HW*HW)       // 50176
#define MP   896           // padded M for 128-tiles

#define TLDH 776           // padded fp16 tile stride (conflict-free, 16B-aligned)
#define DLD  20
#define ELDH 24

// ---------------- scratch ----------------
__device__ __half g_xh [(size_t)Bb*Dm*CHW];
__device__ __half g_qh [BN*Dm];
__device__ __half g_qph[BN*Dm];
__device__ __half g_qkwh[BN*NH*Dm];
__device__ __half g_avnh[BN*NH*Dm];
__device__ __half g_ctxh[BN*Dm];
__device__ __half g_o1h[BN*Dm];
__device__ __half g_h1h[BN*FFD];
__device__ float  g_part[(size_t)4*MP*Dm];      // split-K partials (fc2 only)
#define W_IN_OFF   0
#define W_OUT_OFF  (3*Dm*Dm)
#define W_FC1_OFF  (W_OUT_OFF + Dm*Dm)
#define W_FC2_OFF  (W_FC1_OFF + FFD*Dm)
#define W_TOTAL    (W_FC2_OFF + Dm*FFD)
__device__ __half g_wh[W_TOTAL];

#define MEAN_BLOCKS (Bb*Dm*Tt)
#define F2H_CHUNKS  (W_TOTAL/4)
#define F2H_BLOCKS  ((F2H_CHUNKS + 223)/224)

__device__ __forceinline__ void cp_async16(uint32_t dst, const void* src) {
    asm volatile("cp.async.cg.shared.global [%0], [%1], 16;" :: "r"(dst), "l"(src));
}

// ---------------- fused prep: token means + x->fp16 + weight conversion ----------------
__global__ void prep_kernel(const float* __restrict__ x,
                            const float* __restrict__ s0, const float* __restrict__ s1,
                            const float* __restrict__ s2, const float* __restrict__ s3,
                            __half* __restrict__ wd) {
    int bid = blockIdx.x;
    if (bid >= MEAN_BLOCKS) {
        int chunk = (bid - MEAN_BLOCKS)*224 + threadIdx.x;
        int i = chunk*4;
        if (i >= W_TOTAL) return;
        const float* s; int off;
        if      (i < W_OUT_OFF) { s = s0; off = 0; }
        else if (i < W_FC1_OFF) { s = s1; off = W_OUT_OFF; }
        else if (i < W_FC2_OFF) { s = s2; off = W_FC1_OFF; }
        else                    { s = s3; off = W_FC2_OFF; }
        float4 v = *(const float4*)(s + (i - off));
        ((__half2*)(wd + i))[0] = __floats2half2_rn(v.x, v.y);
        ((__half2*)(wd + i))[1] = __floats2half2_rn(v.z, v.w);
        return;
    }
    int t1 = bid % Tt;
    int dd = (bid / Tt) % Dm;
    int b  = bid / (Tt * Dm);
    size_t base = ((size_t)b*Dm + dd)*CHW + (size_t)t1*16*HW;
    const float4* xp = (const float4*)(x + base);
    __half* xo = g_xh + base;

    int t  = threadIdx.x;
    int qi = t % 56;
    int rg = t / 56;

    float4 acc = make_float4(0.f, 0.f, 0.f, 0.f);
    #pragma unroll
    for (int k = 0; k < 4; k++) {
        int r = rg*4 + k;
        float4 v = xp[r*56 + qi];
        acc.x += v.x; acc.y += v.y; acc.z += v.z; acc.w += v.w;
        __half2 h0 = __floats2half2_rn(v.x, v.y);
        __half2 h1 = __floats2half2_rn(v.z, v.w);
        uint2 u;
        u.x = *(uint32_t*)&h0;
        u.y = *(uint32_t*)&h1;
        *(uint2*)(xo + (size_t)r*HW + qi*4) = u;
    }

    __shared__ float4 ps[224];
    __shared__ float qsum[56];
    ps[t] = acc;
    __syncthreads();
    if (t < 56) {
        float s = 0.f;
        #pragma unroll
        for (int r2 = 0; r2 < 4; r2++) {
            float4 v = ps[r2*56 + t];
            s += v.x + v.y + v.z + v.w;
        }
        qsum[t] = s;
    }
    __syncthreads();
    if (t < Tt) {
        float s = qsum[4*t] + qsum[4*t+1] + qsum[4*t+2] + qsum[4*t+3];
        g_qh[((size_t)b*Np + t1*Tt + t)*Dm + dd] = __float2half(s * (1.0f/256.0f));
    }
}

// ---------------- 128x128 fp16 GEMM (TRANSB) ----------------
__global__ __launch_bounds__(256) void gemm128(
    const __half* __restrict__ A, const __half* __restrict__ Bm,
    float* __restrict__ P, int M, int N, int K, int lda, int ldb, int KS,
    const float* __restrict__ bias, __half* __restrict__ out16, int silu)
{
    extern __shared__ __half dbuf[];
    uint32_t sb = (uint32_t)__cvta_generic_to_shared(dbuf);

    int m0 = blockIdx.y * 128, n0 = blockIdx.x * 128;
    int z = blockIdx.z;
    int Ksub = K / KS;
    int kbase = z * Ksub;
    int tid = threadIdx.x;
    int warpId = tid >> 5;
    int wm = warpId >> 2;
    int wn = warpId & 3;

    wmma::fragment<wmma::accumulator, 16, 16, 16, float> acc[4][2];
    #pragma unroll
    for (int i = 0; i < 4; i++)
        #pragma unroll
        for (int j = 0; j < 2; j++) wmma::fill_fragment(acc[i][j], 0.f);

    const int nk = Ksub >> 6;

    auto issue = [&](int it, int s) {
        int k0 = kbase + it*64;
        uint32_t abase = sb + (uint32_t)(s * 18432 * 2);
        uint32_t bbase = abase + 9216*2;
        #pragma unroll
        for (int i = 0; i < 4; i++) {
            int idx = tid + 256*i;
            int row = idx >> 3, seg = idx & 7;
            int m = m0 + row; if (m >= M) m = M - 1;
            cp_async16(abase + (uint32_t)((row*72 + seg*8)*2),
                       A + (size_t)m*lda + k0 + seg*8);
        }
        #pragma unroll
        for (int i = 0; i < 4; i++) {
            int idx = tid + 256*i;
            int nn = idx >> 3, seg = idx & 7;
            int ng = n0 + nn; if (ng >= N) ng = N - 1;
            cp_async16(bbase + (uint32_t)((nn*72 + seg*8)*2),
                       Bm + (size_t)ng*ldb + k0 + seg*8);
        }
        asm volatile("cp.async.commit_group;");
    };

    issue(0, 0);

    for (int it = 0; it < nk; it++) {
        int s = it & 1;
        if (it + 1 < nk) {
            issue(it+1, s^1);
            asm volatile("cp.async.wait_group 1;");
        } else {
            asm volatile("cp.async.wait_group 0;");
        }
        __syncthreads();

        const __half* As = dbuf + s*18432;
        const __half* Bs = As + 9216;

        #pragma unroll
        for (int ks = 0; ks < 4; ks++) {
            wmma::fragment<wmma::matrix_b, 16, 16, 16, __half, wmma::col_major> bf[2];
            #pragma unroll
            for (int j = 0; j < 2; j++)
                wmma::load_matrix_sync(bf[j], Bs + (wn*32 + j*16)*72 + ks*16, 72);
            #pragma unroll
            for (int i = 0; i < 4; i++) {
                wmma::fragment<wmma::matrix_a, 16, 16, 16, __half, wmma::row_major> af;
                wmma::load_matrix_sync(af, As + (wm*64 + i*16)*72 + ks*16, 72);
                #pragma unroll
                for (int j = 0; j < 2; j++)
                    wmma::mma_sync(acc[i][j], af, bf[j], acc[i][j]);
            }
        }
        __syncthreads();
    }

    if (!bias) {
        float* base = P + (size_t)z*MP*N;
        #pragma unroll
        for (int i = 0; i < 4; i++)
            #pragma unroll
            for (int j = 0; j < 2; j++)
                wmma::store_matrix_sync(base + (size_t)(m0 + wm*64 + i*16)*N + n0 + wn*32 + j*16,
                                        acc[i][j], N, wmma::mem_row_major);
    } else {
        float* Cs = (float*)dbuf;
        #pragma unroll
        for (int i = 0; i < 4; i++)
            #pragma unroll
            for (int j = 0; j < 2; j++)
                wmma::store_matrix_sync(Cs + (wm*64 + i*16)*132 + wn*32 + j*16,
                                        acc[i][j], 132, wmma::mem_row_major);
        __syncthreads();
        #pragma unroll
        for (int i = 0; i < 16; i++) {
            int e = tid + 256*i;
            int row = e >> 5, seg = e & 31;
            int m = m0 + row, nb = n0 + seg*4;
            if (m >= M || nb >= N) continue;
            float4 v = *(const float4*)(Cs + row*132 + seg*4);
            float4 bv = *(const float4*)(bias + nb);
            v.x += bv.x; v.y += bv.y; v.z += bv.z; v.w += bv.w;
            if (silu) {
                v.x = v.x/(1.f+__expf(-v.x)); v.y = v.y/(1.f+__expf(-v.y));
                v.z = v.z/(1.f+__expf(-v.z)); v.w = v.w/(1.f+__expf(-v.w));
            }
            __half2* dst = (__half2*)(out16 + (size_t)m*N + nb);
            dst[0] = __floats2half2_rn(v.x, v.y);
            dst[1] = __floats2half2_rn(v.z, v.w);
        }
    }
}

// ---------------- split-K epilogue (fc2 only) ----------------
__global__ void epi_kernel(const float* __restrict__ P, const float* __restrict__ bias,
                           float* __restrict__ out32, __half* __restrict__ out16,
                           int MN, int N, int KS, float gamma, int silu)
{
    int i = (blockIdx.x*256 + threadIdx.x)*4;
    if (i >= MN) return;
    int c = i % N;
    float4 s = *(const float4*)(P + i);
    for (int ks = 1; ks < KS; ks++) {
        float4 p = *(const float4*)(P + (size_t)ks*MP*N + i);
        s.x += p.x; s.y += p.y; s.z += p.z; s.w += p.w;
    }
    float4 bv = *(const float4*)(bias + c);
    s.x = (s.x + bv.x)*gamma; s.y = (s.y + bv.y)*gamma;
    s.z = (s.z + bv.z)*gamma; s.w = (s.w + bv.w)*gamma;
    if (silu) {
        s.x = s.x/(1.f+__expf(-s.x)); s.y = s.y/(1.f+__expf(-s.y));
        s.z = s.z/(1.f+__expf(-s.z)); s.w = s.w/(1.f+__expf(-s.w));
    }
    if (out32) *(float4*)(out32 + i) = s;
    if (out16) {
        ((__half2*)(out16 + i))[0] = __floats2half2_rn(s.x, s.y);
        ((__half2*)(out16 + i))[1] = __floats2half2_rn(s.z, s.w);
    }
}

// ---------------- 64x64 fp16 GEMM (qp / qkw / ctx / o1; fused epilogue) ----------------
template<bool TRANSB>
__global__ __launch_bounds__(256) void gemm_hc(
    const __half* __restrict__ A, const __half* __restrict__ Bm,
    const float* __restrict__ bias, float* __restrict__ C32, __half* __restrict__ C16,
    int M, int N, int K, int lda, int ldb, int ldc,
    int sAh, int sBh, int sCh, int sBiasH,
    float gamma, int silu)
{
    int h = blockIdx.z;
    A  += (size_t)h * sAh;
    Bm += (size_t)h * sBh;
    const float* biasp = bias ? bias + (size_t)h * sBiasH : nullptr;

    __shared__ __half hbuf[2*2*64*72];
    uint32_t sb = (uint32_t)__cvta_generic_to_shared(hbuf);

    int m0 = blockIdx.y * 64, n0 = blockIdx.x * 64;
    int tid = threadIdx.x;
    int warpId = tid >> 5;
    int wm = warpId >> 1;
    int wn = warpId & 1;

    wmma::fragment<wmma::accumulator, 16, 16, 16, float> cf[2];
    wmma::fill_fragment(cf[0], 0.f);
    wmma::fill_fragment(cf[1], 0.f);

    const int nk = K >> 6;

    auto issue = [&](int it, int s) {
        int k0 = it * 64;
        uint32_t abase = sb + (uint32_t)(s * 9216 * 2);
        uint32_t bbase = abase + 4608*2;
        #pragma unroll
        for (int i = 0; i < 2; i++) {
            int idx = tid + 256*i;
            int row = idx >> 3, seg = idx & 7;
            int m = m0 + row; if (m >= M) m = M - 1;
            cp_async16(abase + (uint32_t)((row*72 + seg*8)*2),
                       A + (size_t)m*lda + k0 + seg*8);
        }
        if (TRANSB) {
            #pragma unroll
            for (int i = 0; i < 2; i++) {
                int idx = tid + 256*i;
                int nn = idx >> 3, seg = idx & 7;
                int ng = n0 + nn; if (ng >= N) ng = N - 1;
                cp_async16(bbase + (uint32_t)((nn*72 + seg*8)*2),
                           Bm + (size_t)ng*ldb + k0 + seg*8);
            }
        } else {
            #pragma unroll
            for (int i = 0; i < 2; i++) {
                int idx = tid + 256*i;
                int kk = idx >> 3, seg = idx & 7;
                int nb = n0 + seg*8; if (nb >= N) nb = 0;
                cp_async16(bbase + (uint32_t)((kk*72 + seg*8)*2),
                           Bm + (size_t)(k0+kk)*ldb + nb);
            }
        }
        asm volatile("cp.async.commit_group;");
    };

    issue(0, 0);

    for (int it = 0; it < nk; it++) {
        int s = it & 1;
        if (it + 1 < nk) {
            issue(it+1, s^1);
            asm volatile("cp.async.wait_group 1;");
        } else {
            asm volatile("cp.async.wait_group 0;");
        }
        __syncthreads();

        const __half* As = hbuf + s*9216;
        const __half* Bs = As + 4608;

        #pragma unroll
        for (int ks = 0; ks < 4; ks++) {
            wmma::fragment<wmma::matrix_a, 16, 16, 16, __half, wmma::row_major> af;
            wmma::load_matrix_sync(af, As + (wm*16)*72 + ks*16, 72);
            #pragma unroll
            for (int j = 0; j < 2; j++) {
                if (TRANSB) {
                    wmma::fragment<wmma::matrix_b, 16, 16, 16, __half, wmma::col_major> bf;
                    wmma::load_matrix_sync(bf, Bs + (wn*32 + j*16)*72 + ks*16, 72);
                    wmma::mma_sync(cf[j], af, bf, cf[j]);
                } else {
                    wmma::fragment<wmma::matrix_b, 16, 16, 16, __half, wmma::row_major> bf;
                    wmma::load_matrix_sync(bf, Bs + (ks*16)*72 + wn*32 + j*16, 72);
                    wmma::mma_sync(cf[j], af, bf, cf[j]);
                }
            }
        }
        __syncthreads();
    }

    float (*Cs)[68] = (float(*)[68])hbuf;
    wmma::store_matrix_sync(&Cs[wm*16][wn*32],      cf[0], 68, wmma::mem_row_major);
    wmma::store_matrix_sync(&Cs[wm*16][wn*32 + 16], cf[1], 68, wmma::mem_row_major);
    __syncthreads();

    #pragma unroll
    for (int i = 0; i < 4; i++) {
        int e = tid + 256*i;
        int row = e >> 4, seg = e & 15;
        int m = m0 + row, nbase = n0 + seg*4;
        if (m >= M || nbase >= N) continue;
        float4 v = *(const float4*)&Cs[row][seg*4];
        if (biasp) {
            float4 bv = *(const float4*)(biasp + nbase);
            v.x += bv.x; v.y += bv.y; v.z += bv.z; v.w += bv.w;
        }
        v.x *= gamma; v.y *= gamma; v.z *= gamma; v.w *= gamma;
        if (silu) {
            v.x = v.x/(1.f+__expf(-v.x)); v.y = v.y/(1.f+__expf(-v.y));
            v.z = v.z/(1.f+__expf(-v.z)); v.w = v.w/(1.f+__expf(-v.w));
        }
        if (C32) *(float4*)(C32 + (size_t)m*ldc + nbase + (size_t)h*sCh) = v;
        if (C16) {
            __half2* dst = (__half2*)(C16 + (size_t)m*ldc + nbase + (size_t)h*sCh);
            dst[0] = __floats2half2_rn(v.x, v.y);
            dst[1] = __floats2half2_rn(v.z, v.w);
        }
    }
}

// ---------------- fused attention v8: warp-specialized scores||AV ----------------
// warps 0-3: scores (K-slice 192 each); warps 4-11: AV for previous chunk (96 cols each).
// smem: qkw 18624 | tiles 3x24832 | Dpart 4x16x20 fp32 (5120) | e_s 768 | e_hr 2x768 | denom 64
// total 100,608 B -> 2 CTAs/SM.
__global__ __launch_bounds__(384, 2) void attn8() {
    extern __shared__ __half smh[];
    __half* qkw_s = smh;                          // [12][TLDH]
    __half* tiles = smh + 12*TLDH;                // 3 x [16][TLDH]
    float*  Dpart = (float*)(smh + 60*TLDH);      // [4][16][DLD]
    float*  e_s   = Dpart + 4*16*DLD;             // [192]
    __half* e_hr  = (__half*)(e_s + 192);         // 2 x [16][ELDH]
    float*  denom = (float*)(e_hr + 2*16*ELDH);   // 16

    int bn = blockIdx.x;
    int b = bn / Np, n = bn % Np;
    int t1 = n / Tt, t2 = n % Tt;
    const __half* xph = g_xh + (size_t)b*Dm*CHW + (size_t)(t1*16)*HW + t2*16;

    int tid = threadIdx.x, w = tid >> 5;

    auto issue_chunk = [&](int lc) {
        uint32_t stp = (uint32_t)__cvta_generic_to_shared(tiles + (lc % 3)*16*TLDH);
        #pragma unroll
        for (int j = 0; j < 4; j++) {
            int ch = tid + 384*j;
            int idx8 = ch*8;
            int r = idx8 / 768, cc = idx8 - r*768;
            int flat = lc*12288 + idx8;
            int dd = flat >> 8, g1 = (flat >> 4) & 15, g2 = flat & 15;
            cp_async16(stp + (uint32_t)((r*TLDH + cc)*2), xph + (size_t)dd*CHW + g1*HW + g2);
        }
        asm volatile("cp.async.commit_group;");
    };

    issue_chunk(0);
    issue_chunk(1);

    {
        const __half* src = g_qkwh + (size_t)bn*(NH*Dm);
        #pragma unroll
        for (int i = 0; i < 3; i++) {
            int idx = tid + 384*i;
            int hh = idx / 96, rem = idx - hh*96;
            *(float4*)(qkw_s + hh*TLDH + rem*8) = *(const float4*)(src + idx*8);
        }
    }
    // zero both e_hr buffers (pad heads 12..15 stay zero)
    e_hr[tid] = __float2half(0.f);
    e_hr[tid + 384] = __float2half(0.f);

    float myden = 0.f;
    int my_r = tid / 12, my_h = tid - my_r*12;

    // A-warps (4..11) each own 96 output columns: 6 accumulator fragments
    wmma::fragment<wmma::accumulator, 16, 16, 16, float> av[6];
    #pragma unroll
    for (int ct = 0; ct < 6; ct++) wmma::fill_fragment(av[ct], 0.f);
    int aw = w - 4;   // 0..7 for A-warps

    for (int i = 0; i < 16; i++) {
        if (i < 15) asm volatile("cp.async.wait_group 1;");
        else        asm volatile("cp.async.wait_group 0;");
        __syncthreads();   // tile(i) ready; e_hr[(i-1)&1] from last interval visible

        if (w < 4) {
            // scores for chunk i: warp w covers k in [w*192, w*192+192)
            const __half* cur = tiles + (i % 3)*16*TLDH;
            wmma::fragment<wmma::accumulator, 16, 16, 16, float> d;
            wmma::fill_fragment(d, 0.f);
            #pragma unroll
            for (int ks = 0; ks < 12; ks++) {
                int k = w*192 + ks*16;
                wmma::fragment<wmma::matrix_a, 16, 16, 16, __half, wmma::row_major> af;
                wmma::load_matrix_sync(af, cur + k, TLDH);
                wmma::fragment<wmma::matrix_b, 16, 16, 16, __half, wmma::col_major> bf;
                wmma::load_matrix_sync(bf, qkw_s + k, TLDH);
                wmma::mma_sync(d, af, bf, d);
            }
            wmma::store_matrix_sync(Dpart + w*16*DLD, d, DLD, wmma::mem_row_major);
        } else if (i >= 1) {
            // AV for chunk i-1 (tile (i-1)%3 live until issue(i+2) after sync B)
            const __half* prev = tiles + ((i-1) % 3)*16*TLDH;
            wmma::fragment<wmma::matrix_a, 16, 16, 16, __half, wmma::row_major> ef;
            wmma::load_matrix_sync(ef, e_hr + ((i-1)&1)*16*ELDH, ELDH);
            #pragma unroll
            for (int ct = 0; ct < 6; ct++) {
                wmma::fragment<wmma::matrix_b, 16, 16, 16, __half, wmma::row_major> vb;
                wmma::load_matrix_sync(vb, prev + aw*96 + ct*16, TLDH);
                wmma::mma_sync(av[ct], ef, vb, av[ct]);
            }
        }
        __syncthreads();   // Dpart ready; AV(i-1) done -> buffer (i-1)%3 free

        if (i + 2 <= 15) issue_chunk(i + 2);   // (i+2)%3 == (i-1)%3

        if (tid < 192) {
            float s = Dpart[my_r*DLD + my_h]
                    + Dpart[16*DLD + my_r*DLD + my_h]
                    + Dpart[2*16*DLD + my_r*DLD + my_h]
                    + Dpart[3*16*DLD + my_r*DLD + my_h];
            float e = __expf(s);
            myden += e;
            e_hr[(i&1)*16*ELDH + my_h*ELDH + my_r] = __float2half(e);
        }
    }

    // tail: AV for chunk 15
    __syncthreads();       // e_hr[15&1] visible
    if (w >= 4) {
        const __half* prev = tiles + (15 % 3)*16*TLDH;
        wmma::fragment<wmma::matrix_a, 16, 16, 16, __half, wmma::row_major> ef;
        wmma::load_matrix_sync(ef, e_hr + (15&1)*16*ELDH, ELDH);
        #pragma unroll
        for (int ct = 0; ct < 6; ct++) {
            wmma::fragment<wmma::matrix_b, 16, 16, 16, __half, wmma::row_major> vb;
            wmma::load_matrix_sync(vb, prev + aw*96 + ct*16, TLDH);
            wmma::mma_sync(av[ct], ef, vb, av[ct]);
        }
    }

    // finalize denominators
    if (tid < 192) e_s[tid] = myden;
    __syncthreads();       // also: AV(15) done before staging clobbers tiles
    if (tid < NH) {
        float d = 0.f;
        #pragma unroll
        for (int r = 0; r < 16; r++) d += e_s[r*12 + tid];
        denom[tid] = d;
    }

    // stage AV accumulators (A-warps), normalize, write fp16
    float* stage = (float*)smh;                // [16][772] fp32 (clobbers qkw/tiles, now dead)
    if (w >= 4) {
        #pragma unroll
        for (int ct = 0; ct < 6; ct++)
            wmma::store_matrix_sync(stage + aw*96 + ct*16, av[ct], 772, wmma::mem_row_major);
    }
    __syncthreads();

    float4 d0 = *(const float4*)(denom);
    float4 d1 = *(const float4*)(denom + 4);
    float4 d2 = *(const float4*)(denom + 8);
    float inv[NH] = {1.f/d0.x, 1.f/d0.y, 1.f/d0.z, 1.f/d0.w,
                     1.f/d1.x, 1.f/d1.y, 1.f/d1.z, 1.f/d1.w,
                     1.f/d2.x, 1.f/d2.y, 1.f/d2.z, 1.f/d2.w};
    #pragma unroll
    for (int hh = 0; hh < NH; hh++) {
        float a = stage[hh*772 + tid*2]     * inv[hh];
        float c = stage[hh*772 + tid*2 + 1] * inv[hh];
        *(__half2*)(g_avnh + (size_t)bn*(NH*Dm) + hh*768 + tid*2) = __floats2half2_rn(a, c);
    }
}

// ---------------- host ----------------
extern "C" void kernel_launch(void* const* d_in, const int* in_sizes, int n_in,
                              void* d_out, int out_size)
{
    const float* x     = (const float*)d_in[0];
    const float* w_in  = (const float*)d_in[1];
    const float* b_in  = (const float*)d_in[2];
    const float* w_out = (const float*)d_in[3];
    const float* b_out = (const float*)d_in[4];
    const float* w_fc1 = (const float*)d_in[5];
    const float* b_fc1 = (const float*)d_in[6];
    const float* w_fc2 = (const float*)d_in[7];
    const float* b_fc2 = (const float*)d_in[8];
    float* y = (float*)d_out;

    __half *qh, *qph, *qkwh, *avnh, *ctxh, *o1h, *h1h, *wh;
    float *part;
    cudaGetSymbolAddress((void**)&qh,   g_qh);
    cudaGetSymbolAddress((void**)&qph,  g_qph);
    cudaGetSymbolAddress((void**)&qkwh, g_qkwh);
    cudaGetSymbolAddress((void**)&avnh, g_avnh);
    cudaGetSymbolAddress((void**)&ctxh, g_ctxh);
    cudaGetSymbolAddress((void**)&o1h,  g_o1h);
    cudaGetSymbolAddress((void**)&h1h,  g_h1h);
    cudaGetSymbolAddress((void**)&wh,   g_wh);
    cudaGetSymbolAddress((void**)&part, g_part);

    const int GSMEM = 2*18432*2;
    cudaFuncSetAttribute(gemm128, cudaFuncAttributeMaxDynamicSharedMemorySize, GSMEM);

    // 0+1. fused weight conversion + token means + x->fp16
    prep_kernel<<<MEAN_BLOCKS + F2H_BLOCKS, 224>>>(x, w_in, w_out, w_fc1, w_fc2, wh);

    // 2. qp = (q @ wq^T + bq)*0.125
    gemm_hc<true><<<dim3(12,13,1), 256>>>(qh, wh + W_IN_OFF, b_in, nullptr, qph,
        BN, Dm, Dm, Dm, Dm, Dm, 0,0,0,0, 0.125f, 0);

    // 3. qkw  (batched heads, K=64)
    gemm_hc<false><<<dim3(12,13,NH), 256>>>(qph, wh + W_IN_OFF + Dm*Dm, nullptr, nullptr, qkwh,
        BN, Dm, HD, Dm, Dm, NH*Dm, HD, HD*Dm, Dm, 0, 1.f, 0);

    // 4. fused attention (warp-specialized)
    {
        static const size_t smem = 100608;
        cudaFuncSetAttribute(attn8, cudaFuncAttributeMaxDynamicSharedMemorySize, (int)smem);
        attn8<<<BN, 384, smem>>>();
    }

    // 5. ctx  (batched heads)
    gemm_hc<true><<<dim3(1,13,NH), 256>>>(avnh, wh + W_IN_OFF + 2*Dm*Dm, b_in + 2*Dm, nullptr, ctxh,
        BN, HD, Dm, NH*Dm, Dm, Dm, Dm, HD*Dm, HD, HD, 1.f, 0);

    // 6. o1 = ctx @ w_out^T + b_out
    gemm_hc<true><<<dim3(12,13,1), 256>>>(ctxh, wh + W_OUT_OFF, b_out, nullptr, o1h,
        BN, Dm, Dm, Dm, Dm, Dm, 0,0,0,0, 1.f, 0);

    // 7. h1 = silu(o1 @ w_fc1^T + b_fc1)
    gemm128<<<dim3(24,7,1), 256, GSMEM>>>(o1h, wh + W_FC1_OFF, part, BN, FFD, Dm, Dm, Dm, 1,
                                          b_fc1, h1h, 1);

    // 8. y = h1 @ w_fc2^T + b_fc2  (split-K 4)
    gemm128<<<dim3(6,7,4), 256, GSMEM>>>(h1h, wh + W_FC2_OFF, part, BN, Dm, FFD, FFD, FFD, 4,
                                         nullptr, nullptr, 0);
    epi_kernel<<<(BN*Dm/4 + 255)/256, 256>>>(part, b_fc2, y, nullptr, BN*Dm, Dm, 4, 1.f, 0);
}

// round 17
// speedup vs baseline: 1.1221x; 1.1175x over previous
#include <cuda_runtime.h>
#include <cuda_fp16.h>
#include <math.h>
#include <stdint.h>
#include <mma.h>

using namespace nvcuda;

#define Bb   4
#define Dm   768
#define Tt   14
#define Np   196
#define NH   12
#define HD   64
#define FFD  3072
#define BN   (Bb*Np)       // 784
#define HW   224
#define CHW  (HW*HW)       // 50176
#define MP   896
#define TOK  196608        // halfs per token patch (256*768)

#define TLDH 776           // padded fp16 tile stride (conflict-free; 1552B = 16B multiple)
#define DLD  20
#define ELDH 24

// ---------------- scratch ----------------
__device__ __half g_xh [(size_t)BN*TOK];        // x fp16, TOKEN-MAJOR: [bn][flat]
__device__ __half g_qh [BN*Dm];
__device__ __half g_qph[BN*Dm];
__device__ __half g_qkwh[BN*NH*Dm];
__device__ __half g_avnh[BN*NH*Dm];
__device__ __half g_ctxh[BN*Dm];
__device__ __half g_o1h[BN*Dm];
__device__ __half g_h1h[BN*FFD];
__device__ float  g_part[(size_t)4*MP*Dm];
#define W_IN_OFF   0
#define W_OUT_OFF  (3*Dm*Dm)
#define W_FC1_OFF  (W_OUT_OFF + Dm*Dm)
#define W_FC2_OFF  (W_FC1_OFF + FFD*Dm)
#define W_TOTAL    (W_FC2_OFF + Dm*FFD)
__device__ __half g_wh[W_TOTAL];

#define MEAN_BLOCKS (Bb*Dm*Tt)
#define F2H_CHUNKS  (W_TOTAL/4)
#define F2H_BLOCKS  ((F2H_CHUNKS + 223)/224)

__device__ __forceinline__ void cp_async16(uint32_t dst, const void* src) {
    asm volatile("cp.async.cg.shared.global [%0], [%1], 16;" :: "r"(dst), "l"(src));
}

// ---------------- fused prep: token means + x->fp16 (token-major) + weight conversion ----------------
__global__ void prep_kernel(const float* __restrict__ x,
                            const float* __restrict__ s0, const float* __restrict__ s1,
                            const float* __restrict__ s2, const float* __restrict__ s3,
                            __half* __restrict__ wd) {
    int bid = blockIdx.x;
    if (bid >= MEAN_BLOCKS) {
        int chunk = (bid - MEAN_BLOCKS)*224 + threadIdx.x;
        int i = chunk*4;
        if (i >= W_TOTAL) return;
        const float* s; int off;
        if      (i < W_OUT_OFF) { s = s0; off = 0; }
        else if (i < W_FC1_OFF) { s = s1; off = W_OUT_OFF; }
        else if (i < W_FC2_OFF) { s = s2; off = W_FC1_OFF; }
        else                    { s = s3; off = W_FC2_OFF; }
        float4 v = *(const float4*)(s + (i - off));
        ((__half2*)(wd + i))[0] = __floats2half2_rn(v.x, v.y);
        ((__half2*)(wd + i))[1] = __floats2half2_rn(v.z, v.w);
        return;
    }
    int t1 = bid % Tt;
    int dd = (bid / Tt) % Dm;
    int b  = bid / (Tt * Dm);
    size_t base = ((size_t)b*Dm + dd)*CHW + (size_t)t1*16*HW;
    const float4* xp = (const float4*)(x + base);
    // token-major output: token bn = b*196 + t1*14 + t2; flat = dd*256 + g1*16 + g2
    __half* xo = g_xh + ((size_t)(b*Np + t1*Tt))*TOK + dd*256;

    int t  = threadIdx.x;      // 0..223
    int qi = t % 56;           // float4 index within row (px cols qi*4..+3)
    int rg = t / 56;
    int t2  = qi >> 2;         // token column
    int g2b = (qi & 3)*4;      // g2 base {0,4,8,12}
    __half* xtok = xo + (size_t)t2*TOK + g2b;

    float4 acc = make_float4(0.f, 0.f, 0.f, 0.f);
    #pragma unroll
    for (int k = 0; k < 4; k++) {
        int r = rg*4 + k;                       // g1
        float4 v = xp[r*56 + qi];
        acc.x += v.x; acc.y += v.y; acc.z += v.z; acc.w += v.w;
        __half2 h0 = __floats2half2_rn(v.x, v.y);
        __half2 h1 = __floats2half2_rn(v.z, v.w);
        uint2 u;
        u.x = *(uint32_t*)&h0;
        u.y = *(uint32_t*)&h1;
        *(uint2*)(xtok + r*16) = u;
    }

    __shared__ float4 ps[224];
    __shared__ float qsum[56];
    ps[t] = acc;
    __syncthreads();
    if (t < 56) {
        float s = 0.f;
        #pragma unroll
        for (int r2 = 0; r2 < 4; r2++) {
            float4 v = ps[r2*56 + t];
            s += v.x + v.y + v.z + v.w;
        }
        qsum[t] = s;
    }
    __syncthreads();
    if (t < Tt) {
        float s = qsum[4*t] + qsum[4*t+1] + qsum[4*t+2] + qsum[4*t+3];
        g_qh[((size_t)b*Np + t1*Tt + t)*Dm + dd] = __float2half(s * (1.0f/256.0f));
    }
}

// ---------------- 128x128 fp16 GEMM (TRANSB) ----------------
__global__ __launch_bounds__(256) void gemm128(
    const __half* __restrict__ A, const __half* __restrict__ Bm,
    float* __restrict__ P, int M, int N, int K, int lda, int ldb, int KS,
    const float* __restrict__ bias, __half* __restrict__ out16, int silu)
{
    extern __shared__ __half dbuf[];
    uint32_t sb = (uint32_t)__cvta_generic_to_shared(dbuf);

    int m0 = blockIdx.y * 128, n0 = blockIdx.x * 128;
    int z = blockIdx.z;
    int Ksub = K / KS;
    int kbase = z * Ksub;
    int tid = threadIdx.x;
    int warpId = tid >> 5;
    int wm = warpId >> 2;
    int wn = warpId & 3;

    wmma::fragment<wmma::accumulator, 16, 16, 16, float> acc[4][2];
    #pragma unroll
    for (int i = 0; i < 4; i++)
        #pragma unroll
        for (int j = 0; j < 2; j++) wmma::fill_fragment(acc[i][j], 0.f);

    const int nk = Ksub >> 6;

    auto issue = [&](int it, int s) {
        int k0 = kbase + it*64;
        uint32_t abase = sb + (uint32_t)(s * 18432 * 2);
        uint32_t bbase = abase + 9216*2;
        #pragma unroll
        for (int i = 0; i < 4; i++) {
            int idx = tid + 256*i;
            int row = idx >> 3, seg = idx & 7;
            int m = m0 + row; if (m >= M) m = M - 1;
            cp_async16(abase + (uint32_t)((row*72 + seg*8)*2),
                       A + (size_t)m*lda + k0 + seg*8);
        }
        #pragma unroll
        for (int i = 0; i < 4; i++) {
            int idx = tid + 256*i;
            int nn = idx >> 3, seg = idx & 7;
            int ng = n0 + nn; if (ng >= N) ng = N - 1;
            cp_async16(bbase + (uint32_t)((nn*72 + seg*8)*2),
                       Bm + (size_t)ng*ldb + k0 + seg*8);
        }
        asm volatile("cp.async.commit_group;");
    };

    issue(0, 0);

    for (int it = 0; it < nk; it++) {
        int s = it & 1;
        if (it + 1 < nk) {
            issue(it+1, s^1);
            asm volatile("cp.async.wait_group 1;");
        } else {
            asm volatile("cp.async.wait_group 0;");
        }
        __syncthreads();

        const __half* As = dbuf + s*18432;
        const __half* Bs = As + 9216;

        #pragma unroll
        for (int ks = 0; ks < 4; ks++) {
            wmma::fragment<wmma::matrix_b, 16, 16, 16, __half, wmma::col_major> bf[2];
            #pragma unroll
            for (int j = 0; j < 2; j++)
                wmma::load_matrix_sync(bf[j], Bs + (wn*32 + j*16)*72 + ks*16, 72);
            #pragma unroll
            for (int i = 0; i < 4; i++) {
                wmma::fragment<wmma::matrix_a, 16, 16, 16, __half, wmma::row_major> af;
                wmma::load_matrix_sync(af, As + (wm*64 + i*16)*72 + ks*16, 72);
                #pragma unroll
                for (int j = 0; j < 2; j++)
                    wmma::mma_sync(acc[i][j], af, bf[j], acc[i][j]);
            }
        }
        __syncthreads();
    }

    if (!bias) {
        float* base = P + (size_t)z*MP*N;
        #pragma unroll
        for (int i = 0; i < 4; i++)
            #pragma unroll
            for (int j = 0; j < 2; j++)
                wmma::store_matrix_sync(base + (size_t)(m0 + wm*64 + i*16)*N + n0 + wn*32 + j*16,
                                        acc[i][j], N, wmma::mem_row_major);
    } else {
        float* Cs = (float*)dbuf;
        #pragma unroll
        for (int i = 0; i < 4; i++)
            #pragma unroll
            for (int j = 0; j < 2; j++)
                wmma::store_matrix_sync(Cs + (wm*64 + i*16)*132 + wn*32 + j*16,
                                        acc[i][j], 132, wmma::mem_row_major);
        __syncthreads();
        #pragma unroll
        for (int i = 0; i < 16; i++) {
            int e = tid + 256*i;
            int row = e >> 5, seg = e & 31;
            int m = m0 + row, nb = n0 + seg*4;
            if (m >= M || nb >= N) continue;
            float4 v = *(const float4*)(Cs + row*132 + seg*4);
            float4 bv = *(const float4*)(bias + nb);
            v.x += bv.x; v.y += bv.y; v.z += bv.z; v.w += bv.w;
            if (silu) {
                v.x = v.x/(1.f+__expf(-v.x)); v.y = v.y/(1.f+__expf(-v.y));
                v.z = v.z/(1.f+__expf(-v.z)); v.w = v.w/(1.f+__expf(-v.w));
            }
            __half2* dst = (__half2*)(out16 + (size_t)m*N + nb);
            dst[0] = __floats2half2_rn(v.x, v.y);
            dst[1] = __floats2half2_rn(v.z, v.w);
        }
    }
}

// ---------------- split-K epilogue (fc2 only) ----------------
__global__ void epi_kernel(const float* __restrict__ P, const float* __restrict__ bias,
                           float* __restrict__ out32, __half* __restrict__ out16,
                           int MN, int N, int KS, float gamma, int silu)
{
    int i = (blockIdx.x*256 + threadIdx.x)*4;
    if (i >= MN) return;
    int c = i % N;
    float4 s = *(const float4*)(P + i);
    for (int ks = 1; ks < KS; ks++) {
        float4 p = *(const float4*)(P + (size_t)ks*MP*N + i);
        s.x += p.x; s.y += p.y; s.z += p.z; s.w += p.w;
    }
    float4 bv = *(const float4*)(bias + c);
    s.x = (s.x + bv.x)*gamma; s.y = (s.y + bv.y)*gamma;
    s.z = (s.z + bv.z)*gamma; s.w = (s.w + bv.w)*gamma;
    if (silu) {
        s.x = s.x/(1.f+__expf(-s.x)); s.y = s.y/(1.f+__expf(-s.y));
        s.z = s.z/(1.f+__expf(-s.z)); s.w = s.w/(1.f+__expf(-s.w));
    }
    if (out32) *(float4*)(out32 + i) = s;
    if (out16) {
        ((__half2*)(out16 + i))[0] = __floats2half2_rn(s.x, s.y);
        ((__half2*)(out16 + i))[1] = __floats2half2_rn(s.z, s.w);
    }
}

// ---------------- 64x64 fp16 GEMM (qp / qkw / ctx / o1) ----------------
template<bool TRANSB>
__global__ __launch_bounds__(256) void gemm_hc(
    const __half* __restrict__ A, const __half* __restrict__ Bm,
    const float* __restrict__ bias, float* __restrict__ C32, __half* __restrict__ C16,
    int M, int N, int K, int lda, int ldb, int ldc,
    int sAh, int sBh, int sCh, int sBiasH,
    float gamma, int silu)
{
    int h = blockIdx.z;
    A  += (size_t)h * sAh;
    Bm += (size_t)h * sBh;
    const float* biasp = bias ? bias + (size_t)h * sBiasH : nullptr;

    __shared__ __half hbuf[2*2*64*72];
    uint32_t sb = (uint32_t)__cvta_generic_to_shared(hbuf);

    int m0 = blockIdx.y * 64, n0 = blockIdx.x * 64;
    int tid = threadIdx.x;
    int warpId = tid >> 5;
    int wm = warpId >> 1;
    int wn = warpId & 1;

    wmma::fragment<wmma::accumulator, 16, 16, 16, float> cf[2];
    wmma::fill_fragment(cf[0], 0.f);
    wmma::fill_fragment(cf[1], 0.f);

    const int nk = K >> 6;

    auto issue = [&](int it, int s) {
        int k0 = it * 64;
        uint32_t abase = sb + (uint32_t)(s * 9216 * 2);
        uint32_t bbase = abase + 4608*2;
        #pragma unroll
        for (int i = 0; i < 2; i++) {
            int idx = tid + 256*i;
            int row = idx >> 3, seg = idx & 7;
            int m = m0 + row; if (m >= M) m = M - 1;
            cp_async16(abase + (uint32_t)((row*72 + seg*8)*2),
                       A + (size_t)m*lda + k0 + seg*8);
        }
        if (TRANSB) {
            #pragma unroll
            for (int i = 0; i < 2; i++) {
                int idx = tid + 256*i;
                int nn = idx >> 3, seg = idx & 7;
                int ng = n0 + nn; if (ng >= N) ng = N - 1;
                cp_async16(bbase + (uint32_t)((nn*72 + seg*8)*2),
                           Bm + (size_t)ng*ldb + k0 + seg*8);
            }
        } else {
            #pragma unroll
            for (int i = 0; i < 2; i++) {
                int idx = tid + 256*i;
                int kk = idx >> 3, seg = idx & 7;
                int nb = n0 + seg*8; if (nb >= N) nb = 0;
                cp_async16(bbase + (uint32_t)((kk*72 + seg*8)*2),
                           Bm + (size_t)(k0+kk)*ldb + nb);
            }
        }
        asm volatile("cp.async.commit_group;");
    };

    issue(0, 0);

    for (int it = 0; it < nk; it++) {
        int s = it & 1;
        if (it + 1 < nk) {
            issue(it+1, s^1);
            asm volatile("cp.async.wait_group 1;");
        } else {
            asm volatile("cp.async.wait_group 0;");
        }
        __syncthreads();

        const __half* As = hbuf + s*9216;
        const __half* Bs = As + 4608;

        #pragma unroll
        for (int ks = 0; ks < 4; ks++) {
            wmma::fragment<wmma::matrix_a, 16, 16, 16, __half, wmma::row_major> af;
            wmma::load_matrix_sync(af, As + (wm*16)*72 + ks*16, 72);
            #pragma unroll
            for (int j = 0; j < 2; j++) {
                if (TRANSB) {
                    wmma::fragment<wmma::matrix_b, 16, 16, 16, __half, wmma::col_major> bf;
                    wmma::load_matrix_sync(bf, Bs + (wn*32 + j*16)*72 + ks*16, 72);
                    wmma::mma_sync(cf[j], af, bf, cf[j]);
                } else {
                    wmma::fragment<wmma::matrix_b, 16, 16, 16, __half, wmma::row_major> bf;
                    wmma::load_matrix_sync(bf, Bs + (ks*16)*72 + wn*32 + j*16, 72);
                    wmma::mma_sync(cf[j], af, bf, cf[j]);
                }
            }
        }
        __syncthreads();
    }

    float (*Cs)[68] = (float(*)[68])hbuf;
    wmma::store_matrix_sync(&Cs[wm*16][wn*32],      cf[0], 68, wmma::mem_row_major);
    wmma::store_matrix_sync(&Cs[wm*16][wn*32 + 16], cf[1], 68, wmma::mem_row_major);
    __syncthreads();

    #pragma unroll
    for (int i = 0; i < 4; i++) {
        int e = tid + 256*i;
        int row = e >> 4, seg = e & 15;
        int m = m0 + row, nbase = n0 + seg*4;
        if (m >= M || nbase >= N) continue;
        float4 v = *(const float4*)&Cs[row][seg*4];
        if (biasp) {
            float4 bv = *(const float4*)(biasp + nbase);
            v.x += bv.x; v.y += bv.y; v.z += bv.z; v.w += bv.w;
        }
        v.x *= gamma; v.y *= gamma; v.z *= gamma; v.w *= gamma;
        if (silu) {
            v.x = v.x/(1.f+__expf(-v.x)); v.y = v.y/(1.f+__expf(-v.y));
            v.z = v.z/(1.f+__expf(-v.z)); v.w = v.w/(1.f+__expf(-v.w));
        }
        if (C32) *(float4*)(C32 + (size_t)m*ldc + nbase + (size_t)h*sCh) = v;
        if (C16) {
            __half2* dst = (__half2*)(C16 + (size_t)m*ldc + nbase + (size_t)h*sCh);
            dst[0] = __floats2half2_rn(v.x, v.y);
            dst[1] = __floats2half2_rn(v.z, v.w);
        }
    }
}

// ---------------- fused attention v9: R14 structure + bulk-async tile loads ----------------
// smem: qkw 18624 | tiles 3x24832 | Dpart 15360 | e_s 768 | e_hr 768 | denom 64 | mbar 24 = 110104 B
__global__ __launch_bounds__(384, 2) void attn9() {
    extern __shared__ __half smh[];
    __half*   qkw_s = smh;                         // [12][TLDH]
    __half*   tiles = smh + 12*TLDH;               // 3 x [16][TLDH]
    float*    Dpart = (float*)(smh + 60*TLDH);     // [12][16][DLD]
    float*    e_s   = Dpart + 12*16*DLD;           // [192]
    __half*   e_hr  = (__half*)(e_s + 192);        // [16][ELDH]
    float*    denom = (float*)(e_hr + 16*ELDH);    // 16
    uint64_t* mbar  = (uint64_t*)(denom + 16);     // 3

    int bn = blockIdx.x;
    const __half* xsrc = g_xh + (size_t)bn*TOK;    // token-major, rows contiguous

    int tid = threadIdx.x, w = tid >> 5;
    uint32_t tiles_sa = (uint32_t)__cvta_generic_to_shared(tiles);
    uint32_t mbar_sa  = (uint32_t)__cvta_generic_to_shared(mbar);

    if (tid == 0) {
        #pragma unroll
        for (int i = 0; i < 3; i++)
            asm volatile("mbarrier.init.shared.b64 [%0], 1;" :: "r"(mbar_sa + i*8) : "memory");
    }
    __syncthreads();

    auto issue_chunk = [&](int lc) {               // one thread only
        uint32_t mb = mbar_sa + (lc % 3)*8;
        asm volatile("mbarrier.arrive.expect_tx.shared.b64 _, [%0], %1;"
                     :: "r"(mb), "r"(24576u) : "memory");
        uint32_t dst = tiles_sa + (uint32_t)((lc % 3)*16*TLDH*2);
        const __half* src = xsrc + (size_t)lc*12288;
        #pragma unroll
        for (int r = 0; r < 16; r++) {
            asm volatile(
                "cp.async.bulk.shared::cta.global.mbarrier::complete_tx::bytes "
                "[%0], [%1], %2, [%3];"
                :: "r"(dst + (uint32_t)(r*TLDH*2)), "l"(src + r*768),
                   "r"(1536u), "r"(mb) : "memory");
        }
    };

    if (tid == 0) { issue_chunk(0); issue_chunk(1); }

    {   // stage qkw (overlaps bulk fetch)
        const __half* src = g_qkwh + (size_t)bn*(NH*Dm);
        #pragma unroll
        for (int i = 0; i < 3; i++) {
            int idx = tid + 384*i;
            int hh = idx / 96, rem = idx - hh*96;
            *(float4*)(qkw_s + hh*TLDH + rem*8) = *(const float4*)(src + idx*8);
        }
    }
    if (tid < 16*ELDH) e_hr[tid] = __float2half(0.f);

    float myden = 0.f;
    int my_r = tid / 12, my_h = tid - my_r*12;

    wmma::fragment<wmma::accumulator, 16, 16, 16, float> av[4];
    #pragma unroll
    for (int ct = 0; ct < 4; ct++) wmma::fill_fragment(av[ct], 0.f);

    for (int lc = 0; lc < 16; lc++) {
        const __half* cur = tiles + (lc % 3)*16*TLDH;
        // wait for chunk lc (all threads)
        {
            uint32_t mb = mbar_sa + (lc % 3)*8;
            uint32_t parity = (uint32_t)((lc/3) & 1);
            uint32_t done;
            asm volatile(
                "{\n\t.reg .pred p;\n\t"
                "mbarrier.try_wait.parity.acquire.cta.shared::cta.b64 p, [%1], %2;\n\t"
                "selp.b32 %0, 1, 0, p;\n\t}"
                : "=r"(done) : "r"(mb), "r"(parity) : "memory");
            if (!done) {
                asm volatile(
                    "{\n\t.reg .pred P1;\n\t"
                    "WAIT_LOOP_%=:\n\t"
                    "mbarrier.try_wait.parity.acquire.cta.shared::cta.b64 P1, [%0], %1, 0x989680;\n\t"
                    "@P1 bra.uni WAIT_DONE_%=;\n\t"
                    "bra.uni WAIT_LOOP_%=;\n\t"
                    "WAIT_DONE_%=:\n\t}"
                    :: "r"(mb), "r"(parity) : "memory");
            }
        }
        __syncthreads();                           // all warps past AV(lc-1); Dpart/e_hr reusable
        if (tid == 0 && lc + 2 <= 15) issue_chunk(lc + 2);   // refills buffer (lc-1)%3

        // scores: warp w handles k-slice [64w, 64w+64)
        {
            wmma::fragment<wmma::accumulator, 16, 16, 16, float> d;
            wmma::fill_fragment(d, 0.f);
            #pragma unroll
            for (int ks = 0; ks < 4; ks++) {
                int k = w*64 + ks*16;
                wmma::fragment<wmma::matrix_a, 16, 16, 16, __half, wmma::row_major> af;
                wmma::load_matrix_sync(af, cur + k, TLDH);
                wmma::fragment<wmma::matrix_b, 16, 16, 16, __half, wmma::col_major> bf;
                wmma::load_matrix_sync(bf, qkw_s + k, TLDH);
                wmma::mma_sync(d, af, bf, d);
            }
            wmma::store_matrix_sync(Dpart + w*16*DLD, d, DLD, wmma::mem_row_major);
        }
        __syncthreads();

        if (tid < 192) {
            float s = 0.f;
            #pragma unroll
            for (int w2 = 0; w2 < 12; w2++) s += Dpart[w2*16*DLD + my_r*DLD + my_h];
            float e = __expf(s);
            myden += e;
            e_hr[my_h*ELDH + my_r] = __float2half(e);
        }
        __syncthreads();

        {
            wmma::fragment<wmma::matrix_a, 16, 16, 16, __half, wmma::row_major> ef;
            wmma::load_matrix_sync(ef, e_hr, ELDH);
            #pragma unroll
            for (int ct = 0; ct < 4; ct++) {
                wmma::fragment<wmma::matrix_b, 16, 16, 16, __half, wmma::row_major> vb;
                wmma::load_matrix_sync(vb, cur + w*64 + ct*16, TLDH);
                wmma::mma_sync(av[ct], ef, vb, av[ct]);
            }
        }
    }

    // finalize denominators
    if (tid < 192) e_s[tid] = myden;
    __syncthreads();
    if (tid < NH) {
        float d = 0.f;
        #pragma unroll
        for (int r = 0; r < 16; r++) d += e_s[r*12 + tid];
        denom[tid] = d;
    }

    // stage AV accumulators, normalize, write fp16
    float* stage = (float*)smh;                // [16][772]
    #pragma unroll
    for (int ct = 0; ct < 4; ct++)
        wmma::store_matrix_sync(stage + w*64 + ct*16, av[ct], 772, wmma::mem_row_major);
    __syncthreads();

    float4 d0 = *(const float4*)(denom);
    float4 d1 = *(const float4*)(denom + 4);
    float4 d2 = *(const float4*)(denom + 8);
    float inv[NH] = {1.f/d0.x, 1.f/d0.y, 1.f/d0.z, 1.f/d0.w,
                     1.f/d1.x, 1.f/d1.y, 1.f/d1.z, 1.f/d1.w,
                     1.f/d2.x, 1.f/d2.y, 1.f/d2.z, 1.f/d2.w};
    #pragma unroll
    for (int hh = 0; hh < NH; hh++) {
        float a = stage[hh*772 + tid*2]     * inv[hh];
        float c = stage[hh*772 + tid*2 + 1] * inv[hh];
        *(__half2*)(g_avnh + (size_t)bn*(NH*Dm) + hh*768 + tid*2) = __floats2half2_rn(a, c);
    }
}

// ---------------- host ----------------
extern "C" void kernel_launch(void* const* d_in, const int* in_sizes, int n_in,
                              void* d_out, int out_size)
{
    const float* x     = (const float*)d_in[0];
    const float* w_in  = (const float*)d_in[1];
    const float* b_in  = (const float*)d_in[2];
    const float* w_out = (const float*)d_in[3];
    const float* b_out = (const float*)d_in[4];
    const float* w_fc1 = (const float*)d_in[5];
    const float* b_fc1 = (const float*)d_in[6];
    const float* w_fc2 = (const float*)d_in[7];
    const float* b_fc2 = (const float*)d_in[8];
    float* y = (float*)d_out;

    __half *qh, *qph, *qkwh, *avnh, *ctxh, *o1h, *h1h, *wh;
    float *part;
    cudaGetSymbolAddress((void**)&qh,   g_qh);
    cudaGetSymbolAddress((void**)&qph,  g_qph);
    cudaGetSymbolAddress((void**)&qkwh, g_qkwh);
    cudaGetSymbolAddress((void**)&avnh, g_avnh);
    cudaGetSymbolAddress((void**)&ctxh, g_ctxh);
    cudaGetSymbolAddress((void**)&o1h,  g_o1h);
    cudaGetSymbolAddress((void**)&h1h,  g_h1h);
    cudaGetSymbolAddress((void**)&wh,   g_wh);
    cudaGetSymbolAddress((void**)&part, g_part);

    const int GSMEM = 2*18432*2;
    cudaFuncSetAttribute(gemm128, cudaFuncAttributeMaxDynamicSharedMemorySize, GSMEM);

    // 0+1. fused weight conversion + token means + x->fp16 (token-major)
    prep_kernel<<<MEAN_BLOCKS + F2H_BLOCKS, 224>>>(x, w_in, w_out, w_fc1, w_fc2, wh);

    // 2. qp = (q @ wq^T + bq)*0.125
    gemm_hc<true><<<dim3(12,13,1), 256>>>(qh, wh + W_IN_OFF, b_in, nullptr, qph,
        BN, Dm, Dm, Dm, Dm, Dm, 0,0,0,0, 0.125f, 0);

    // 3. qkw  (batched heads, K=64)
    gemm_hc<false><<<dim3(12,13,NH), 256>>>(qph, wh + W_IN_OFF + Dm*Dm, nullptr, nullptr, qkwh,
        BN, Dm, HD, Dm, Dm, NH*Dm, HD, HD*Dm, Dm, 0, 1.f, 0);

    // 4. fused attention (bulk-async tiles)
    {
        static const size_t smem = 110104;
        cudaFuncSetAttribute(attn9, cudaFuncAttributeMaxDynamicSharedMemorySize, (int)smem);
        attn9<<<BN, 384, smem>>>();
    }

    // 5. ctx  (batched heads)
    gemm_hc<true><<<dim3(1,13,NH), 256>>>(avnh, wh + W_IN_OFF + 2*Dm*Dm, b_in + 2*Dm, nullptr, ctxh,
        BN, HD, Dm, NH*Dm, Dm, Dm, Dm, HD*Dm, HD, HD, 1.f, 0);

    // 6. o1 = ctx @ w_out^T + b_out
    gemm_hc<true><<<dim3(12,13,1), 256>>>(ctxh, wh + W_OUT_OFF, b_out, nullptr, o1h,
        BN, Dm, Dm, Dm, Dm, Dm, 0,0,0,0, 1.f, 0);

    // 7. h1 = silu(o1 @ w_fc1^T + b_fc1)
    gemm128<<<dim3(24,7,1), 256, GSMEM>>>(o1h, wh + W_FC1_OFF, part, BN, FFD, Dm, Dm, Dm, 1,
                                          b_fc1, h1h, 1);

    // 8. y = h1 @ w_fc2^T + b_fc2  (split-K 4)
    gemm128<<<dim3(6,7,4), 256, GSMEM>>>(h1h, wh + W_FC2_OFF, part, BN, Dm, FFD, FFD, FFD, 4,
                                         nullptr, nullptr, 0);
    epi_kernel<<<(BN*Dm/4 + 255)/256, 256>>>(part, b_fc2, y, nullptr, BN*Dm, Dm, 4, 1.f, 0);
}